// round 7
// baseline (speedup 1.0000x reference)
#include <cuda_runtime.h>

#define L1LEN 512
#define L2LEN 512
#define DDIM  256
#define BATCH 2
#define NG    16
#define GS    16
#define TI    8
#define TJ    32           // source rows per tile
#define NHALF 8            // tiles per CTA (256 j per CTA half)
#define KSTR  260          // padded V row stride (floats)
#define NSTR  20           // sc2 inner stride
#define NTHR  256

__device__ float g_Q[BATCH * L1LEN * DDIM];
__device__ float g_K[BATCH * L2LEN * DDIM];
__device__ float g_V[BATCH * L2LEN * DDIM];
__device__ float g_pacc[BATCH * 64 * 2 * TI * DDIM];   // partial outputs
__device__ float g_pl[BATCH * 64 * 2 * TI * NG];       // partial exp-sums

// ---------------------------------------------------------------------------
// QKV projection: y[m][e] = sum_d x[m][d] * W[e][d]   (M=1024, N=256, K=256)
// 32x64 tile, BK=32 double-buffered, 128 threads, 4x4 micro-tile.
// Grid (32, 4, 3) = 384 CTAs.
// ---------------------------------------------------------------------------
__global__ __launch_bounds__(128) void qkv_gemm(const float* __restrict__ x_target,
                                                const float* __restrict__ x_source,
                                                const float* __restrict__ Wq,
                                                const float* __restrict__ Wk,
                                                const float* __restrict__ Wv) {
    const int z = blockIdx.z;
    const float* __restrict__ x = (z == 0) ? x_target : x_source;
    const float* __restrict__ W = (z == 0) ? Wq : ((z == 1) ? Wk : Wv);
    float* __restrict__ y       = (z == 0) ? g_Q : ((z == 1) ? g_K : g_V);

    __shared__ float xs[2][32][36];   // [buf][k][m]
    __shared__ float ws[2][32][68];   // [buf][k][n]

    const int t  = threadIdx.x;
    const int tx = t & 15;            // n micro (16 x 4 = 64)
    const int ty = t >> 4;            // m micro (8 x 4 = 32)
    const int m_blk = blockIdx.x * 32;
    const int n_blk = blockIdx.y * 64;

    // loader indexing (coalesced float4)
    const int xi = t;                 // +128 -> 2 loads, row = idx>>3, col=(idx&7)*4
    float4 xr[2], wr[4];

    float c[4][4] = {};

#define LOADT(k0)                                                              \
    {                                                                          \
        _Pragma("unroll")                                                      \
        for (int i = 0; i < 2; i++) {                                          \
            int idx = xi + i * 128;                                            \
            xr[i] = *(const float4*)&x[(m_blk + (idx >> 3)) * DDIM + (k0) +    \
                                       (idx & 7) * 4];                         \
        }                                                                      \
        _Pragma("unroll")                                                      \
        for (int i = 0; i < 4; i++) {                                          \
            int idx = xi + i * 128;                                            \
            wr[i] = *(const float4*)&W[(n_blk + (idx >> 3)) * DDIM + (k0) +    \
                                       (idx & 7) * 4];                         \
        }                                                                      \
    }

#define STORET(buf)                                                            \
    {                                                                          \
        _Pragma("unroll")                                                      \
        for (int i = 0; i < 2; i++) {                                          \
            int idx = xi + i * 128;                                            \
            int row = idx >> 3, k = (idx & 7) * 4;                             \
            xs[buf][k + 0][row] = xr[i].x; xs[buf][k + 1][row] = xr[i].y;      \
            xs[buf][k + 2][row] = xr[i].z; xs[buf][k + 3][row] = xr[i].w;      \
        }                                                                      \
        _Pragma("unroll")                                                      \
        for (int i = 0; i < 4; i++) {                                          \
            int idx = xi + i * 128;                                            \
            int row = idx >> 3, k = (idx & 7) * 4;                             \
            ws[buf][k + 0][row] = wr[i].x; ws[buf][k + 1][row] = wr[i].y;      \
            ws[buf][k + 2][row] = wr[i].z; ws[buf][k + 3][row] = wr[i].w;      \
        }                                                                      \
    }

    LOADT(0);
    STORET(0);
    __syncthreads();

#pragma unroll
    for (int kt = 0; kt < 8; kt++) {
        const int cur = kt & 1;
        if (kt < 7) LOADT((kt + 1) * 32);
#pragma unroll
        for (int kk = 0; kk < 32; kk++) {
            float4 a  = *(const float4*)&xs[cur][kk][ty * 4];
            float4 bq = *(const float4*)&ws[cur][kk][tx * 4];
            float av[4] = {a.x, a.y, a.z, a.w};
            float bv[4] = {bq.x, bq.y, bq.z, bq.w};
#pragma unroll
            for (int r = 0; r < 4; r++)
#pragma unroll
                for (int cc = 0; cc < 4; cc++)
                    c[r][cc] += av[r] * bv[cc];
        }
        if (kt < 7) {
            STORET(1 - cur);
            __syncthreads();
        }
    }

#pragma unroll
    for (int r = 0; r < 4; r++) {
        float4 o = make_float4(c[r][0], c[r][1], c[r][2], c[r][3]);
        *(float4*)&y[(m_blk + ty * 4 + r) * DDIM + n_blk + tx * 4] = o;
    }
}

// ---------------------------------------------------------------------------
// Fused attention, j-split across 2 CTAs, no-max softmax (scores bounded).
// 256 threads, 2 CTAs/SM. Grid 256 = BATCH * 64 * 2.
// K is NOT staged: phase B reads its row directly from gmem (L1-cached).
//   B: thread (jj in 32, nc in 8): scores for 8 i x 2 groups, exp -> sc2
//   sum: t<128 accumulates sum_j exp (concurrent with D)
//   D: thread (qp,ip,jh): 2 i-rows x 8 dims x 16 j, unnormalized accumulate
// ---------------------------------------------------------------------------
__global__ __launch_bounds__(NTHR, 2) void attn_kernel(const float* __restrict__ wmlp,
                                                       const float* __restrict__ bmlp) {
    extern __shared__ float sm[];
    float* q   = sm;                        // 2048
    float* vt  = q + TI * DDIM;             // 32*260 = 8320
    float* sc2 = vt + TJ * KSTR;            // 8*32*20 = 5120  [(i*TJ+j)*NSTR + n]

    const int t     = threadIdx.x;
    const int bx    = blockIdx.x;
    const int b     = bx >> 7;
    const int itile = (bx >> 1) & 63;
    const int jh2   = bx & 1;               // j half: 0 -> [0,256), 1 -> [256,512)
    const int i_base = itile * TI;
    const int part   = bx;                  // partial slot

    // phase B ids
    const int jj = t & 31;
    const int nc = t >> 5;                  // 0..7 -> groups 2nc, 2nc+1
    // phase D ids
    const int qp = t & 31;                  // d-quad: d = 4qp and 4qp+128
    const int ip = (t >> 5) & 3;            // i rows: ip, ip+4
    const int jh = t >> 7;                  // j-split 0..1 (16 j each)
    const int n0 = (4 * qp) & 15;

    float w[GS];
#pragma unroll
    for (int g = 0; g < GS; g++) w[g] = wmlp[g];
    const float b0 = bmlp[0];

    // load Q block
    {
        const float* Qg = g_Q + (b * L1LEN + i_base) * DDIM;
#pragma unroll
        for (int it = 0; it < 2; it++) {
            int idx = t + it * NTHR;
            int row = idx >> 6, col = (idx & 63) * 4;
            *(float4*)&q[row * DDIM + col] = *(const float4*)&Qg[row * DDIM + col];
        }
    }

    float acc[2][2][4] = {};
    float lsum = 0.f;                       // valid on t<128: (i=t>>4, n=t&15)

    for (int tile = 0; tile < NHALF; tile++) {
        __syncthreads();
        const int j_glob = jh2 * (L2LEN / 2) + tile * TJ;
        // ---- Phase A: stage V tile only
        {
            const float* Vg = g_V + (b * L2LEN + j_glob) * DDIM;
#pragma unroll
            for (int it = 0; it < (TJ * DDIM / 4) / NTHR; it++) {
                int idx = t + it * NTHR;
                int row = idx >> 6, col = (idx & 63) * 4;
                *(float4*)&vt[row * KSTR + col] = *(const float4*)&Vg[row * DDIM + col];
            }
        }

        // ---- Phase B: scores + exp -> sc2 (K direct from gmem, Q broadcast)
        {
            const float* kr = g_K + (b * L2LEN + j_glob + jj) * DDIM;
            float kv[8][4];
#pragma unroll
            for (int n2 = 0; n2 < 2; n2++)
#pragma unroll
                for (int dq = 0; dq < 4; dq++) {
                    float4 kq = *(const float4*)&kr[(nc * 2 + n2) * GS + dq * 4];
                    kv[n2 * 4 + dq][0] = kq.x; kv[n2 * 4 + dq][1] = kq.y;
                    kv[n2 * 4 + dq][2] = kq.z; kv[n2 * 4 + dq][3] = kq.w;
                }
            float s[8][2];
#pragma unroll
            for (int i = 0; i < 8; i++) { s[i][0] = 0.f; s[i][1] = 0.f; }
#pragma unroll
            for (int n2 = 0; n2 < 2; n2++) {
                const int n = nc * 2 + n2;
#pragma unroll
                for (int dq = 0; dq < 4; dq++) {
                    const int d = n * GS + dq * 4;
                    const float k0 = kv[n2 * 4 + dq][0], k1 = kv[n2 * 4 + dq][1];
                    const float k2 = kv[n2 * 4 + dq][2], k3 = kv[n2 * 4 + dq][3];
                    const float w0 = w[dq * 4 + 0], w1 = w[dq * 4 + 1];
                    const float w2 = w[dq * 4 + 2], w3 = w[dq * 4 + 3];
#pragma unroll
                    for (int i = 0; i < 8; i++) {
                        float4 qv = *(const float4*)&q[i * DDIM + d];
                        s[i][n2] += fmaxf(qv.x - k0, 0.f) * w0
                                  + fmaxf(qv.y - k1, 0.f) * w1
                                  + fmaxf(qv.z - k2, 0.f) * w2
                                  + fmaxf(qv.w - k3, 0.f) * w3;
                    }
                }
            }
#pragma unroll
            for (int i = 0; i < 8; i++) {
#pragma unroll
                for (int n2 = 0; n2 < 2; n2++) {
                    sc2[(i * TJ + jj) * NSTR + nc * 2 + n2] =
                        __expf(fmaxf(s[i][n2] + b0, 0.f));
                }
            }
        }
        __syncthreads();

        // ---- exp-sum (t<128, concurrent with D; no barrier between them)
        if (t < TI * NG) {
            const int ci = t >> 4, cn = t & 15;
            const float* base = sc2 + ci * TJ * NSTR + cn;
            float s0 = 0.f, s1 = 0.f;
#pragma unroll
            for (int j = 0; j < TJ; j += 2) {
                s0 += base[j * NSTR];
                s1 += base[(j + 1) * NSTR];
            }
            lsum += s0 + s1;
        }

        // ---- Phase D: unnormalized accumulate
        {
            const int j0 = jh * (TJ / 2);
#pragma unroll 4
            for (int jo = 0; jo < TJ / 2; jo++) {
                const int j = j0 + jo;
                float4 p0 = *(const float4*)&sc2[(ip * TJ + j) * NSTR + n0];
                float4 p1 = *(const float4*)&sc2[((ip + 4) * TJ + j) * NSTR + n0];
                float4 v0 = *(const float4*)&vt[j * KSTR + 4 * qp];
                float4 v1 = *(const float4*)&vt[j * KSTR + 4 * qp + 128];
                acc[0][0][0] += p0.x * v0.x; acc[0][0][1] += p0.y * v0.y;
                acc[0][0][2] += p0.z * v0.z; acc[0][0][3] += p0.w * v0.w;
                acc[0][1][0] += p0.x * v1.x; acc[0][1][1] += p0.y * v1.y;
                acc[0][1][2] += p0.z * v1.z; acc[0][1][3] += p0.w * v1.w;
                acc[1][0][0] += p1.x * v0.x; acc[1][0][1] += p1.y * v0.y;
                acc[1][0][2] += p1.z * v0.z; acc[1][0][3] += p1.w * v0.w;
                acc[1][1][0] += p1.x * v1.x; acc[1][1][1] += p1.y * v1.y;
                acc[1][1][2] += p1.z * v1.z; acc[1][1][3] += p1.w * v1.w;
            }
        }
    }

    // ---- merge jh halves in smem, write partials to global scratch
    __syncthreads();
    if (jh == 1) {
        float* scr = sc2;  // reuse: 128 slots * 16 floats
        int base = (ip * 32 + qp) * 16;
        *(float4*)&scr[base + 0]  = *(float4*)&acc[0][0][0];
        *(float4*)&scr[base + 4]  = *(float4*)&acc[0][1][0];
        *(float4*)&scr[base + 8]  = *(float4*)&acc[1][0][0];
        *(float4*)&scr[base + 12] = *(float4*)&acc[1][1][0];
    }
    __syncthreads();
    if (jh == 0) {
        float* scr = sc2;
        int base = (ip * 32 + qp) * 16;
        float4 a00 = *(float4*)&scr[base + 0];
        float4 a01 = *(float4*)&scr[base + 4];
        float4 a10 = *(float4*)&scr[base + 8];
        float4 a11 = *(float4*)&scr[base + 12];
        float* pb = g_pacc + part * (TI * DDIM);
        *(float4*)&pb[ip * DDIM + 4 * qp] =
            make_float4(acc[0][0][0] + a00.x, acc[0][0][1] + a00.y,
                        acc[0][0][2] + a00.z, acc[0][0][3] + a00.w);
        *(float4*)&pb[ip * DDIM + 4 * qp + 128] =
            make_float4(acc[0][1][0] + a01.x, acc[0][1][1] + a01.y,
                        acc[0][1][2] + a01.z, acc[0][1][3] + a01.w);
        *(float4*)&pb[(ip + 4) * DDIM + 4 * qp] =
            make_float4(acc[1][0][0] + a10.x, acc[1][0][1] + a10.y,
                        acc[1][0][2] + a10.z, acc[1][0][3] + a10.w);
        *(float4*)&pb[(ip + 4) * DDIM + 4 * qp + 128] =
            make_float4(acc[1][1][0] + a11.x, acc[1][1][1] + a11.y,
                        acc[1][1][2] + a11.z, acc[1][1][3] + a11.w);
    }
    if (t < TI * NG) g_pl[part * (TI * NG) + t] = lsum;
}

// ---------------------------------------------------------------------------
// Merge: out = (acc_half0 + acc_half1) / (l_half0 + l_half1)
// ---------------------------------------------------------------------------
__global__ __launch_bounds__(256) void merge_kernel(float* __restrict__ out) {
    const int bx = blockIdx.x;              // (b*64 + itile)
    const int t  = threadIdx.x;
    const int p0 = bx * 2, p1 = bx * 2 + 1;
    const float* a0 = g_pacc + p0 * (TI * DDIM);
    const float* a1 = g_pacc + p1 * (TI * DDIM);
    const float* l0 = g_pl + p0 * (TI * NG);
    const float* l1 = g_pl + p1 * (TI * NG);
    float* ob = out + bx * (TI * DDIM);

#pragma unroll
    for (int k = 0; k < 2; k++) {
        int idx = t + k * 256;              // 0..511 float4 slots
        int i   = idx >> 6;
        int d0  = (idx & 63) * 4;
        int nq  = d0 & 15;
        float4 x0 = *(const float4*)&a0[i * DDIM + d0];
        float4 x1 = *(const float4*)&a1[i * DDIM + d0];
        float4 u0 = *(const float4*)&l0[i * NG + nq];
        float4 u1 = *(const float4*)&l1[i * NG + nq];
        float4 r;
        r.x = (x0.x + x1.x) / (u0.x + u1.x);
        r.y = (x0.y + x1.y) / (u0.y + u1.y);
        r.z = (x0.z + x1.z) / (u0.z + u1.z);
        r.w = (x0.w + x1.w) / (u0.w + u1.w);
        *(float4*)&ob[i * DDIM + d0] = r;
    }
}

// ---------------------------------------------------------------------------
extern "C" void kernel_launch(void* const* d_in, const int* in_sizes, int n_in,
                              void* d_out, int out_size) {
    const float* x_source = (const float*)d_in[0];
    const float* x_target = (const float*)d_in[1];
    const float* Wq       = (const float*)d_in[2];
    const float* Wk       = (const float*)d_in[3];
    const float* Wv       = (const float*)d_in[4];
    const float* w_mlp    = (const float*)d_in[5];
    const float* b_mlp    = (const float*)d_in[6];
    float* out            = (float*)d_out;

    dim3 ggrid(32, 4, 3);
    qkv_gemm<<<ggrid, 128>>>(x_target, x_source, Wq, Wk, Wv);

    const size_t smem_bytes =
        (TI * DDIM + TJ * KSTR + TI * TJ * NSTR) * sizeof(float);
    cudaFuncSetAttribute(attn_kernel, cudaFuncAttributeMaxDynamicSharedMemorySize,
                         (int)smem_bytes);
    attn_kernel<<<BATCH * 64 * 2, NTHR, smem_bytes>>>(w_mlp, b_mlp);

    merge_kernel<<<BATCH * 64, 256>>>(out);
}

// round 9
// speedup vs baseline: 1.0596x; 1.0596x over previous
#include <cuda_runtime.h>
#include <cstdint>

#define L1LEN 512
#define L2LEN 512
#define DDIM  256
#define BATCH 2
#define NG    16
#define GS    16
#define TI    8
#define TJ    32           // source rows per tile
#define NHALF 8            // tiles per CTA (256 j per CTA half)
#define KSTR  260          // padded V row stride (floats)
#define NSTR  20           // sc2 inner stride
#define NTHR  256

__device__ float g_Q[BATCH * L1LEN * DDIM];
__device__ float g_K[BATCH * L2LEN * DDIM];
__device__ float g_V[BATCH * L2LEN * DDIM];
__device__ float g_pacc[BATCH * 64 * 2 * TI * DDIM];   // partial outputs
__device__ float g_pl[BATCH * 64 * 2 * TI * NG];       // partial exp-sums

// ---------------------------------------------------------------------------
// QKV projection via tensor cores, 3xTF32 error-compensated.
// y[m][e] = sum_d x[m][d] * W[e][d]   (M=1024, N=256, K=256) x 3 matrices.
// CTA: 128 threads (4 warps), tile 64x32 (warp = m16n32). Grid (16,8,3)=384.
// Each fp32 operand split hi/lo in tf32; acc = hi*hi + hi*lo + lo*hi (~1e-7).
// ---------------------------------------------------------------------------
__device__ __forceinline__ uint32_t f2tf32(float f) {
    uint32_t r;
    asm("cvt.rna.tf32.f32 %0, %1;" : "=r"(r) : "f"(f));
    return r;
}

__device__ __forceinline__ void mma_tf32(float* c, const uint32_t* a,
                                         uint32_t b0, uint32_t b1) {
    asm("mma.sync.aligned.m16n8k8.row.col.f32.tf32.tf32.f32 "
        "{%0,%1,%2,%3}, {%4,%5,%6,%7}, {%8,%9}, {%0,%1,%2,%3};"
        : "+f"(c[0]), "+f"(c[1]), "+f"(c[2]), "+f"(c[3])
        : "r"(a[0]), "r"(a[1]), "r"(a[2]), "r"(a[3]), "r"(b0), "r"(b1));
}

__global__ __launch_bounds__(128) void qkv_gemm(const float* __restrict__ x_target,
                                                const float* __restrict__ x_source,
                                                const float* __restrict__ Wq,
                                                const float* __restrict__ Wk,
                                                const float* __restrict__ Wv) {
    const int z = blockIdx.z;
    const float* __restrict__ x = (z == 0) ? x_target : x_source;
    const float* __restrict__ W = (z == 0) ? Wq : ((z == 1) ? Wk : Wv);
    float* __restrict__ y       = (z == 0) ? g_Q : ((z == 1) ? g_K : g_V);

    __shared__ float xs[64][36];   // [m][k] fp32, BK=32 (+4 pad)
    __shared__ float ws[32][36];   // [n][k] fp32

    const int t    = threadIdx.x;
    const int warp = t >> 5;       // 0..3 -> m16 row block
    const int lane = t & 31;
    const int gid  = lane >> 2;    // 0..7
    const int tig  = lane & 3;     // 0..3
    const int m_blk = blockIdx.x * 64;
    const int n_blk = blockIdx.y * 32;

    float acc[4][4] = {};          // [nb][c-reg] : warp tile m16 x n32

    for (int chunk = 0; chunk < 8; chunk++) {
        const int kc = chunk * 32;
        __syncthreads();
        // stage x (64x32) and W (32x32), coalesced float4
#pragma unroll
        for (int i = 0; i < 4; i++) {
            int idx = t + i * 128;
            int row = idx >> 3, col = (idx & 7) * 4;
            *(float4*)&xs[row][col] =
                *(const float4*)&x[(m_blk + row) * DDIM + kc + col];
        }
#pragma unroll
        for (int i = 0; i < 2; i++) {
            int idx = t + i * 128;
            int row = idx >> 3, col = (idx & 7) * 4;
            *(float4*)&ws[row][col] =
                *(const float4*)&W[(n_blk + row) * DDIM + kc + col];
        }
        __syncthreads();

#pragma unroll
        for (int ks = 0; ks < 4; ks++) {
            const int k0 = ks * 8;
            // A fragment (m16k8): conflict-free scalar LDS
            float af[4];
            af[0] = xs[warp * 16 + gid][k0 + tig];
            af[1] = xs[warp * 16 + gid + 8][k0 + tig];
            af[2] = xs[warp * 16 + gid][k0 + tig + 4];
            af[3] = xs[warp * 16 + gid + 8][k0 + tig + 4];
            uint32_t ahi[4], alo[4];
#pragma unroll
            for (int j = 0; j < 4; j++) {
                ahi[j] = f2tf32(af[j]);
                alo[j] = f2tf32(af[j] - __uint_as_float(ahi[j]));
            }
#pragma unroll
            for (int nb = 0; nb < 4; nb++) {
                float bf0 = ws[nb * 8 + gid][k0 + tig];
                float bf1 = ws[nb * 8 + gid][k0 + tig + 4];
                uint32_t bhi0 = f2tf32(bf0);
                uint32_t blo0 = f2tf32(bf0 - __uint_as_float(bhi0));
                uint32_t bhi1 = f2tf32(bf1);
                uint32_t blo1 = f2tf32(bf1 - __uint_as_float(bhi1));
                mma_tf32(acc[nb], ahi, bhi0, bhi1);
                mma_tf32(acc[nb], ahi, blo0, blo1);
                mma_tf32(acc[nb], alo, bhi0, bhi1);
            }
        }
    }

    // write out: c0/c1 -> (row gid, cols 2tig,2tig+1); c2/c3 -> row gid+8
    const int m = m_blk + warp * 16 + gid;
#pragma unroll
    for (int nb = 0; nb < 4; nb++) {
        const int n = n_blk + nb * 8 + 2 * tig;
        *(float2*)&y[m * DDIM + n]       = make_float2(acc[nb][0], acc[nb][1]);
        *(float2*)&y[(m + 8) * DDIM + n] = make_float2(acc[nb][2], acc[nb][3]);
    }
}

// ---------------------------------------------------------------------------
// Fused attention, j-split across 2 CTAs, no-max softmax (scores bounded).
// 256 threads, 2 CTAs/SM. Grid 256 = BATCH * 64 * 2.
// K is NOT staged: phase B reads its row directly from gmem (L1-cached).
// ---------------------------------------------------------------------------
__global__ __launch_bounds__(NTHR, 2) void attn_kernel(const float* __restrict__ wmlp,
                                                       const float* __restrict__ bmlp) {
    extern __shared__ float sm[];
    float* q   = sm;                        // 2048
    float* vt  = q + TI * DDIM;             // 32*260 = 8320
    float* sc2 = vt + TJ * KSTR;            // 8*32*20 = 5120  [(i*TJ+j)*NSTR + n]

    const int t     = threadIdx.x;
    const int bx    = blockIdx.x;
    const int b     = bx >> 7;
    const int itile = (bx >> 1) & 63;
    const int jh2   = bx & 1;               // j half: 0 -> [0,256), 1 -> [256,512)
    const int i_base = itile * TI;
    const int part   = bx;                  // partial slot

    const int jj = t & 31;
    const int nc = t >> 5;                  // 0..7 -> groups 2nc, 2nc+1
    const int qp = t & 31;                  // d-quad: d = 4qp and 4qp+128
    const int ip = (t >> 5) & 3;            // i rows: ip, ip+4
    const int jh = t >> 7;                  // j-split 0..1 (16 j each)
    const int n0 = (4 * qp) & 15;

    float w[GS];
#pragma unroll
    for (int g = 0; g < GS; g++) w[g] = wmlp[g];
    const float b0 = bmlp[0];

    {
        const float* Qg = g_Q + (b * L1LEN + i_base) * DDIM;
#pragma unroll
        for (int it = 0; it < 2; it++) {
            int idx = t + it * NTHR;
            int row = idx >> 6, col = (idx & 63) * 4;
            *(float4*)&q[row * DDIM + col] = *(const float4*)&Qg[row * DDIM + col];
        }
    }

    float acc[2][2][4] = {};
    float lsum = 0.f;

    for (int tile = 0; tile < NHALF; tile++) {
        __syncthreads();
        const int j_glob = jh2 * (L2LEN / 2) + tile * TJ;
        {
            const float* Vg = g_V + (b * L2LEN + j_glob) * DDIM;
#pragma unroll
            for (int it = 0; it < (TJ * DDIM / 4) / NTHR; it++) {
                int idx = t + it * NTHR;
                int row = idx >> 6, col = (idx & 63) * 4;
                *(float4*)&vt[row * KSTR + col] = *(const float4*)&Vg[row * DDIM + col];
            }
        }

        {
            const float* kr = g_K + (b * L2LEN + j_glob + jj) * DDIM;
            float kv[8][4];
#pragma unroll
            for (int n2 = 0; n2 < 2; n2++)
#pragma unroll
                for (int dq = 0; dq < 4; dq++) {
                    float4 kq = *(const float4*)&kr[(nc * 2 + n2) * GS + dq * 4];
                    kv[n2 * 4 + dq][0] = kq.x; kv[n2 * 4 + dq][1] = kq.y;
                    kv[n2 * 4 + dq][2] = kq.z; kv[n2 * 4 + dq][3] = kq.w;
                }
            float s[8][2];
#pragma unroll
            for (int i = 0; i < 8; i++) { s[i][0] = 0.f; s[i][1] = 0.f; }
#pragma unroll
            for (int n2 = 0; n2 < 2; n2++) {
                const int n = nc * 2 + n2;
#pragma unroll
                for (int dq = 0; dq < 4; dq++) {
                    const int d = n * GS + dq * 4;
                    const float k0 = kv[n2 * 4 + dq][0], k1 = kv[n2 * 4 + dq][1];
                    const float k2 = kv[n2 * 4 + dq][2], k3 = kv[n2 * 4 + dq][3];
                    const float w0 = w[dq * 4 + 0], w1 = w[dq * 4 + 1];
                    const float w2 = w[dq * 4 + 2], w3 = w[dq * 4 + 3];
#pragma unroll
                    for (int i = 0; i < 8; i++) {
                        float4 qv = *(const float4*)&q[i * DDIM + d];
                        s[i][n2] += fmaxf(qv.x - k0, 0.f) * w0
                                  + fmaxf(qv.y - k1, 0.f) * w1
                                  + fmaxf(qv.z - k2, 0.f) * w2
                                  + fmaxf(qv.w - k3, 0.f) * w3;
                    }
                }
            }
#pragma unroll
            for (int i = 0; i < 8; i++) {
#pragma unroll
                for (int n2 = 0; n2 < 2; n2++) {
                    sc2[(i * TJ + jj) * NSTR + nc * 2 + n2] =
                        __expf(fmaxf(s[i][n2] + b0, 0.f));
                }
            }
        }
        __syncthreads();

        if (t < TI * NG) {
            const int ci = t >> 4, cn = t & 15;
            const float* base = sc2 + ci * TJ * NSTR + cn;
            float s0 = 0.f, s1 = 0.f;
#pragma unroll
            for (int j = 0; j < TJ; j += 2) {
                s0 += base[j * NSTR];
                s1 += base[(j + 1) * NSTR];
            }
            lsum += s0 + s1;
        }

        {
            const int j0 = jh * (TJ / 2);
#pragma unroll 4
            for (int jo = 0; jo < TJ / 2; jo++) {
                const int j = j0 + jo;
                float4 p0 = *(const float4*)&sc2[(ip * TJ + j) * NSTR + n0];
                float4 p1 = *(const float4*)&sc2[((ip + 4) * TJ + j) * NSTR + n0];
                float4 v0 = *(const float4*)&vt[j * KSTR + 4 * qp];
                float4 v1 = *(const float4*)&vt[j * KSTR + 4 * qp + 128];
                acc[0][0][0] += p0.x * v0.x; acc[0][0][1] += p0.y * v0.y;
                acc[0][0][2] += p0.z * v0.z; acc[0][0][3] += p0.w * v0.w;
                acc[0][1][0] += p0.x * v1.x; acc[0][1][1] += p0.y * v1.y;
                acc[0][1][2] += p0.z * v1.z; acc[0][1][3] += p0.w * v1.w;
                acc[1][0][0] += p1.x * v0.x; acc[1][0][1] += p1.y * v0.y;
                acc[1][0][2] += p1.z * v0.z; acc[1][0][3] += p1.w * v0.w;
                acc[1][1][0] += p1.x * v1.x; acc[1][1][1] += p1.y * v1.y;
                acc[1][1][2] += p1.z * v1.z; acc[1][1][3] += p1.w * v1.w;
            }
        }
    }

    __syncthreads();
    if (jh == 1) {
        float* scr = sc2;
        int base = (ip * 32 + qp) * 16;
        *(float4*)&scr[base + 0]  = *(float4*)&acc[0][0][0];
        *(float4*)&scr[base + 4]  = *(float4*)&acc[0][1][0];
        *(float4*)&scr[base + 8]  = *(float4*)&acc[1][0][0];
        *(float4*)&scr[base + 12] = *(float4*)&acc[1][1][0];
    }
    __syncthreads();
    if (jh == 0) {
        float* scr = sc2;
        int base = (ip * 32 + qp) * 16;
        float4 a00 = *(float4*)&scr[base + 0];
        float4 a01 = *(float4*)&scr[base + 4];
        float4 a10 = *(float4*)&scr[base + 8];
        float4 a11 = *(float4*)&scr[base + 12];
        float* pb = g_pacc + part * (TI * DDIM);
        *(float4*)&pb[ip * DDIM + 4 * qp] =
            make_float4(acc[0][0][0] + a00.x, acc[0][0][1] + a00.y,
                        acc[0][0][2] + a00.z, acc[0][0][3] + a00.w);
        *(float4*)&pb[ip * DDIM + 4 * qp + 128] =
            make_float4(acc[0][1][0] + a01.x, acc[0][1][1] + a01.y,
                        acc[0][1][2] + a01.z, acc[0][1][3] + a01.w);
        *(float4*)&pb[(ip + 4) * DDIM + 4 * qp] =
            make_float4(acc[1][0][0] + a10.x, acc[1][0][1] + a10.y,
                        acc[1][0][2] + a10.z, acc[1][0][3] + a10.w);
        *(float4*)&pb[(ip + 4) * DDIM + 4 * qp + 128] =
            make_float4(acc[1][1][0] + a11.x, acc[1][1][1] + a11.y,
                        acc[1][1][2] + a11.z, acc[1][1][3] + a11.w);
    }
    if (t < TI * NG) g_pl[part * (TI * NG) + t] = lsum;
}

// ---------------------------------------------------------------------------
// Merge: out = (acc_half0 + acc_half1) / (l_half0 + l_half1)
// ---------------------------------------------------------------------------
__global__ __launch_bounds__(256) void merge_kernel(float* __restrict__ out) {
    const int bx = blockIdx.x;
    const int t  = threadIdx.x;
    const int p0 = bx * 2, p1 = bx * 2 + 1;
    const float* a0 = g_pacc + p0 * (TI * DDIM);
    const float* a1 = g_pacc + p1 * (TI * DDIM);
    const float* l0 = g_pl + p0 * (TI * NG);
    const float* l1 = g_pl + p1 * (TI * NG);
    float* ob = out + bx * (TI * DDIM);

#pragma unroll
    for (int k = 0; k < 2; k++) {
        int idx = t + k * 256;
        int i   = idx >> 6;
        int d0  = (idx & 63) * 4;
        int nq  = d0 & 15;
        float4 x0 = *(const float4*)&a0[i * DDIM + d0];
        float4 x1 = *(const float4*)&a1[i * DDIM + d0];
        float4 u0 = *(const float4*)&l0[i * NG + nq];
        float4 u1 = *(const float4*)&l1[i * NG + nq];
        float4 r;
        r.x = (x0.x + x1.x) / (u0.x + u1.x);
        r.y = (x0.y + x1.y) / (u0.y + u1.y);
        r.z = (x0.z + x1.z) / (u0.z + u1.z);
        r.w = (x0.w + x1.w) / (u0.w + u1.w);
        *(float4*)&ob[i * DDIM + d0] = r;
    }
}

// ---------------------------------------------------------------------------
extern "C" void kernel_launch(void* const* d_in, const int* in_sizes, int n_in,
                              void* d_out, int out_size) {
    const float* x_source = (const float*)d_in[0];
    const float* x_target = (const float*)d_in[1];
    const float* Wq       = (const float*)d_in[2];
    const float* Wk       = (const float*)d_in[3];
    const float* Wv       = (const float*)d_in[4];
    const float* w_mlp    = (const float*)d_in[5];
    const float* b_mlp    = (const float*)d_in[6];
    float* out            = (float*)d_out;

    dim3 ggrid(16, 8, 3);
    qkv_gemm<<<ggrid, 128>>>(x_target, x_source, Wq, Wk, Wv);

    const size_t smem_bytes =
        (TI * DDIM + TJ * KSTR + TI * TJ * NSTR) * sizeof(float);
    cudaFuncSetAttribute(attn_kernel, cudaFuncAttributeMaxDynamicSharedMemorySize,
                         (int)smem_bytes);
    attn_kernel<<<BATCH * 64 * 2, NTHR, smem_bytes>>>(w_mlp, b_mlp);

    merge_kernel<<<BATCH * 64, 256>>>(out);
}

// round 10
// speedup vs baseline: 1.0760x; 1.0154x over previous
#include <cuda_runtime.h>
#include <cstdint>

#define L1LEN 512
#define L2LEN 512
#define DDIM  256
#define BATCH 2
#define NG    16
#define GS    16
#define TI    8
#define TJ    32           // source rows per tile
#define NHALF 8            // tiles per CTA (256 j per CTA half)
#define KSTR  256          // V row stride (floats)
#define NSTR  20           // sc2 inner stride
#define NTHR  256

__device__ float g_Q[BATCH * L1LEN * DDIM];
__device__ float g_K[BATCH * L2LEN * DDIM];
__device__ float g_V[BATCH * L2LEN * DDIM];
__device__ float g_pacc[BATCH * 64 * 2 * TI * DDIM];   // partial outputs
__device__ float g_pl[BATCH * 64 * 2 * TI * NG];       // partial exp-sums

// ---------------------------------------------------------------------------
// QKV projection via tensor cores, 3xTF32 error-compensated.
// W tile pre-split into tf32 hi/lo planes in smem (convert once, use 4x).
// CTA: 128 threads (4 warps), tile 64x32. Grid (16,8,3)=384.
// ---------------------------------------------------------------------------
__device__ __forceinline__ uint32_t f2tf32(float f) {
    uint32_t r;
    asm("cvt.rna.tf32.f32 %0, %1;" : "=r"(r) : "f"(f));
    return r;
}

__device__ __forceinline__ void mma_tf32(float* c, const uint32_t* a,
                                         uint32_t b0, uint32_t b1) {
    asm("mma.sync.aligned.m16n8k8.row.col.f32.tf32.tf32.f32 "
        "{%0,%1,%2,%3}, {%4,%5,%6,%7}, {%8,%9}, {%0,%1,%2,%3};"
        : "+f"(c[0]), "+f"(c[1]), "+f"(c[2]), "+f"(c[3])
        : "r"(a[0]), "r"(a[1]), "r"(a[2]), "r"(a[3]), "r"(b0), "r"(b1));
}

__global__ __launch_bounds__(128) void qkv_gemm(const float* __restrict__ x_target,
                                                const float* __restrict__ x_source,
                                                const float* __restrict__ Wq,
                                                const float* __restrict__ Wk,
                                                const float* __restrict__ Wv) {
    const int z = blockIdx.z;
    const float* __restrict__ x = (z == 0) ? x_target : x_source;
    const float* __restrict__ W = (z == 0) ? Wq : ((z == 1) ? Wk : Wv);
    float* __restrict__ y       = (z == 0) ? g_Q : ((z == 1) ? g_K : g_V);

    __shared__ float    xs[64][36];    // [m][k] fp32
    __shared__ uint32_t wsh[32][36];   // [n][k] tf32 hi
    __shared__ uint32_t wsl[32][36];   // [n][k] tf32 lo

    const int t    = threadIdx.x;
    const int warp = t >> 5;
    const int lane = t & 31;
    const int gid  = lane >> 2;
    const int tig  = lane & 3;
    const int m_blk = blockIdx.x * 64;
    const int n_blk = blockIdx.y * 32;

    float acc[4][4] = {};

    for (int chunk = 0; chunk < 8; chunk++) {
        const int kc = chunk * 32;
        __syncthreads();
#pragma unroll
        for (int i = 0; i < 4; i++) {
            int idx = t + i * 128;
            int row = idx >> 3, col = (idx & 7) * 4;
            *(float4*)&xs[row][col] =
                *(const float4*)&x[(m_blk + row) * DDIM + kc + col];
        }
#pragma unroll
        for (int i = 0; i < 2; i++) {
            int idx = t + i * 128;
            int row = idx >> 3, col = (idx & 7) * 4;
            float4 wv = *(const float4*)&W[(n_blk + row) * DDIM + kc + col];
            uint32_t h0 = f2tf32(wv.x), h1 = f2tf32(wv.y);
            uint32_t h2 = f2tf32(wv.z), h3 = f2tf32(wv.w);
            wsh[row][col + 0] = h0; wsh[row][col + 1] = h1;
            wsh[row][col + 2] = h2; wsh[row][col + 3] = h3;
            wsl[row][col + 0] = f2tf32(wv.x - __uint_as_float(h0));
            wsl[row][col + 1] = f2tf32(wv.y - __uint_as_float(h1));
            wsl[row][col + 2] = f2tf32(wv.z - __uint_as_float(h2));
            wsl[row][col + 3] = f2tf32(wv.w - __uint_as_float(h3));
        }
        __syncthreads();

#pragma unroll
        for (int ks = 0; ks < 4; ks++) {
            const int k0 = ks * 8;
            float af[4];
            af[0] = xs[warp * 16 + gid][k0 + tig];
            af[1] = xs[warp * 16 + gid + 8][k0 + tig];
            af[2] = xs[warp * 16 + gid][k0 + tig + 4];
            af[3] = xs[warp * 16 + gid + 8][k0 + tig + 4];
            uint32_t ahi[4], alo[4];
#pragma unroll
            for (int j = 0; j < 4; j++) {
                ahi[j] = f2tf32(af[j]);
                alo[j] = f2tf32(af[j] - __uint_as_float(ahi[j]));
            }
#pragma unroll
            for (int nb = 0; nb < 4; nb++) {
                uint32_t bhi0 = wsh[nb * 8 + gid][k0 + tig];
                uint32_t bhi1 = wsh[nb * 8 + gid][k0 + tig + 4];
                uint32_t blo0 = wsl[nb * 8 + gid][k0 + tig];
                uint32_t blo1 = wsl[nb * 8 + gid][k0 + tig + 4];
                mma_tf32(acc[nb], ahi, bhi0, bhi1);
                mma_tf32(acc[nb], ahi, blo0, blo1);
                mma_tf32(acc[nb], alo, bhi0, bhi1);
            }
        }
    }

    const int m = m_blk + warp * 16 + gid;
#pragma unroll
    for (int nb = 0; nb < 4; nb++) {
        const int n = n_blk + nb * 8 + 2 * tig;
        *(float2*)&y[m * DDIM + n]       = make_float2(acc[nb][0], acc[nb][1]);
        *(float2*)&y[(m + 8) * DDIM + n] = make_float2(acc[nb][2], acc[nb][3]);
    }
}

// ---------------------------------------------------------------------------
// Fused attention, j-split across 2 CTAs, no-max softmax.
// 256 threads, 2 CTAs/SM. Grid 256 = BATCH * 64 * 2.
//   B: thread (jj, nc): scores for 8 i x 2 groups, exp -> sc2
//   D: warp (ih, jq): 4 i-rows x 8 j x full 256 d (vt read amp 4x -> 2x)
// ---------------------------------------------------------------------------
__global__ __launch_bounds__(NTHR, 2) void attn_kernel(const float* __restrict__ wmlp,
                                                       const float* __restrict__ bmlp) {
    extern __shared__ float sm[];
    float* q   = sm;                        // 2048
    float* vt  = q + TI * DDIM;             // 32*256 = 8192 (reused as scratch)
    float* sc2 = vt + TJ * KSTR;            // 8*32*20 = 5120  [(i*TJ+j)*NSTR + n]

    const int t     = threadIdx.x;
    const int bx    = blockIdx.x;
    const int b     = bx >> 7;
    const int itile = (bx >> 1) & 63;
    const int jh2   = bx & 1;               // j half: 0 -> [0,256), 1 -> [256,512)
    const int i_base = itile * TI;
    const int part   = bx;                  // partial slot

    const int jj = t & 31;
    const int nc = t >> 5;                  // 0..7 -> groups 2nc, 2nc+1
    // phase D ids: warp = (ih, jq)
    const int qp = t & 31;
    const int ih = (t >> 5) & 1;            // i rows 4*ih .. 4*ih+3
    const int jq = t >> 6;                  // j quarter 0..3 (8 j each)
    const int n0 = (4 * qp) & 15;

    float w[GS];
#pragma unroll
    for (int g = 0; g < GS; g++) w[g] = wmlp[g];
    const float b0 = bmlp[0];

    {
        const float* Qg = g_Q + (b * L1LEN + i_base) * DDIM;
#pragma unroll
        for (int it = 0; it < 2; it++) {
            int idx = t + it * NTHR;
            int row = idx >> 6, col = (idx & 63) * 4;
            *(float4*)&q[row * DDIM + col] = *(const float4*)&Qg[row * DDIM + col];
        }
    }

    float acc[4][2][4] = {};   // [i-row r][d-quad][comp]
    float lsum = 0.f;          // valid on t<128

    for (int tile = 0; tile < NHALF; tile++) {
        __syncthreads();
        const int j_glob = jh2 * (L2LEN / 2) + tile * TJ;
        // ---- Phase A: stage V tile (overlaps with B below; no barrier between)
        {
            const float* Vg = g_V + (b * L2LEN + j_glob) * DDIM;
#pragma unroll
            for (int it = 0; it < (TJ * DDIM / 4) / NTHR; it++) {
                int idx = t + it * NTHR;
                int row = idx >> 6, col = (idx & 63) * 4;
                *(float4*)&vt[row * KSTR + col] = *(const float4*)&Vg[row * DDIM + col];
            }
        }

        // ---- Phase B: scores + exp -> sc2 (K direct from gmem, Q broadcast)
        {
            const float* kr = g_K + (b * L2LEN + j_glob + jj) * DDIM;
            float kv[8][4];
#pragma unroll
            for (int n2 = 0; n2 < 2; n2++)
#pragma unroll
                for (int dq = 0; dq < 4; dq++) {
                    float4 kq = *(const float4*)&kr[(nc * 2 + n2) * GS + dq * 4];
                    kv[n2 * 4 + dq][0] = kq.x; kv[n2 * 4 + dq][1] = kq.y;
                    kv[n2 * 4 + dq][2] = kq.z; kv[n2 * 4 + dq][3] = kq.w;
                }
            float s[8][2];
#pragma unroll
            for (int i = 0; i < 8; i++) { s[i][0] = 0.f; s[i][1] = 0.f; }
#pragma unroll
            for (int n2 = 0; n2 < 2; n2++) {
                const int n = nc * 2 + n2;
#pragma unroll
                for (int dq = 0; dq < 4; dq++) {
                    const int d = n * GS + dq * 4;
                    const float k0 = kv[n2 * 4 + dq][0], k1 = kv[n2 * 4 + dq][1];
                    const float k2 = kv[n2 * 4 + dq][2], k3 = kv[n2 * 4 + dq][3];
                    const float w0 = w[dq * 4 + 0], w1 = w[dq * 4 + 1];
                    const float w2 = w[dq * 4 + 2], w3 = w[dq * 4 + 3];
#pragma unroll
                    for (int i = 0; i < 8; i++) {
                        float4 qv = *(const float4*)&q[i * DDIM + d];
                        s[i][n2] += fmaxf(qv.x - k0, 0.f) * w0
                                  + fmaxf(qv.y - k1, 0.f) * w1
                                  + fmaxf(qv.z - k2, 0.f) * w2
                                  + fmaxf(qv.w - k3, 0.f) * w3;
                    }
                }
            }
#pragma unroll
            for (int i = 0; i < 8; i++) {
#pragma unroll
                for (int n2 = 0; n2 < 2; n2++) {
                    sc2[(i * TJ + jj) * NSTR + nc * 2 + n2] =
                        __expf(fmaxf(s[i][n2] + b0, 0.f));
                }
            }
        }
        __syncthreads();

        // ---- exp-sum (t<128, overlaps with D)
        if (t < TI * NG) {
            const int ci = t >> 4, cn = t & 15;
            const float* base = sc2 + ci * TJ * NSTR + cn;
            float s0 = 0.f, s1 = 0.f;
#pragma unroll
            for (int j = 0; j < TJ; j += 2) {
                s0 += base[j * NSTR];
                s1 += base[(j + 1) * NSTR];
            }
            lsum += s0 + s1;
        }

        // ---- Phase D: warp (ih,jq): 4 i-rows x 8 j x full d
        {
            const int j0 = jq * 8;
#pragma unroll
            for (int jo = 0; jo < 8; jo++) {
                const int j = j0 + jo;
                float4 v0 = *(const float4*)&vt[j * KSTR + 4 * qp];
                float4 v1 = *(const float4*)&vt[j * KSTR + 4 * qp + 128];
#pragma unroll
                for (int r = 0; r < 4; r++) {
                    float4 p = *(const float4*)&sc2[((4 * ih + r) * TJ + j) * NSTR + n0];
                    acc[r][0][0] += p.x * v0.x; acc[r][0][1] += p.y * v0.y;
                    acc[r][0][2] += p.z * v0.z; acc[r][0][3] += p.w * v0.w;
                    acc[r][1][0] += p.x * v1.x; acc[r][1][1] += p.y * v1.y;
                    acc[r][1][2] += p.z * v1.z; acc[r][1][3] += p.w * v1.w;
                }
            }
        }
    }

    // ---- reduce jq partials via vt scratch, write partials to global
    __syncthreads();
    {
        // slot layout: warp (t>>5) * 1024 + qp * 32 + r*8 + quad*4
        float* scr = vt;
        int base = (t >> 5) * 1024 + qp * 32;
#pragma unroll
        for (int r = 0; r < 4; r++) {
            *(float4*)&scr[base + r * 8]     = *(float4*)&acc[r][0][0];
            *(float4*)&scr[base + r * 8 + 4] = *(float4*)&acc[r][1][0];
        }
    }
    __syncthreads();
    {
        // thread t owns (i = t>>5, qp = t&31); sum 4 jq partials
        const int i  = t >> 5;
        const int mih = i >> 2, r = i & 3;
        const float* scr = vt;
        float4 s0 = make_float4(0.f, 0.f, 0.f, 0.f);
        float4 s1 = make_float4(0.f, 0.f, 0.f, 0.f);
#pragma unroll
        for (int jqq = 0; jqq < 4; jqq++) {
            const int wslot = mih + 2 * jqq + ((jqq >= 2) ? 2 : 0); // warp = ih + (jq<<1)... see below
        }
        // warp index for (ih, jq): t>>5 = ih + 2*... NOTE: ih=(w)&1, jq=w>>1? No:
        // ih=(t>>5)&1, jq=t>>6 -> w = ih + 2*jq. So partial for (mih, jqq) is warp mih+2*jqq.
#pragma unroll
        for (int jqq = 0; jqq < 4; jqq++) {
            const int wv = mih + 2 * jqq;
            const float* pbase = scr + wv * 1024 + (t & 31) * 32 + r * 8;
            float4 a0 = *(const float4*)&pbase[0];
            float4 a1 = *(const float4*)&pbase[4];
            s0.x += a0.x; s0.y += a0.y; s0.z += a0.z; s0.w += a0.w;
            s1.x += a1.x; s1.y += a1.y; s1.z += a1.z; s1.w += a1.w;
        }
        float* pb = g_pacc + part * (TI * DDIM);
        *(float4*)&pb[i * DDIM + 4 * (t & 31)]       = s0;
        *(float4*)&pb[i * DDIM + 4 * (t & 31) + 128] = s1;
    }
    if (t < TI * NG) g_pl[part * (TI * NG) + t] = lsum;
}

// ---------------------------------------------------------------------------
// Merge: out = (acc_half0 + acc_half1) / (l_half0 + l_half1)
// ---------------------------------------------------------------------------
__global__ __launch_bounds__(256) void merge_kernel(float* __restrict__ out) {
    const int bx = blockIdx.x;
    const int t  = threadIdx.x;
    const int p0 = bx * 2, p1 = bx * 2 + 1;
    const float* a0 = g_pacc + p0 * (TI * DDIM);
    const float* a1 = g_pacc + p1 * (TI * DDIM);
    const float* l0 = g_pl + p0 * (TI * NG);
    const float* l1 = g_pl + p1 * (TI * NG);
    float* ob = out + bx * (TI * DDIM);

#pragma unroll
    for (int k = 0; k < 2; k++) {
        int idx = t + k * 256;
        int i   = idx >> 6;
        int d0  = (idx & 63) * 4;
        int nq  = d0 & 15;
        float4 x0 = *(const float4*)&a0[i * DDIM + d0];
        float4 x1 = *(const float4*)&a1[i * DDIM + d0];
        float4 u0 = *(const float4*)&l0[i * NG + nq];
        float4 u1 = *(const float4*)&l1[i * NG + nq];
        float4 r;
        r.x = (x0.x + x1.x) / (u0.x + u1.x);
        r.y = (x0.y + x1.y) / (u0.y + u1.y);
        r.z = (x0.z + x1.z) / (u0.z + u1.z);
        r.w = (x0.w + x1.w) / (u0.w + u1.w);
        *(float4*)&ob[i * DDIM + d0] = r;
    }
}

// ---------------------------------------------------------------------------
extern "C" void kernel_launch(void* const* d_in, const int* in_sizes, int n_in,
                              void* d_out, int out_size) {
    const float* x_source = (const float*)d_in[0];
    const float* x_target = (const float*)d_in[1];
    const float* Wq       = (const float*)d_in[2];
    const float* Wk       = (const float*)d_in[3];
    const float* Wv       = (const float*)d_in[4];
    const float* w_mlp    = (const float*)d_in[5];
    const float* b_mlp    = (const float*)d_in[6];
    float* out            = (float*)d_out;

    dim3 ggrid(16, 8, 3);
    qkv_gemm<<<ggrid, 128>>>(x_target, x_source, Wq, Wk, Wv);

    const size_t smem_bytes =
        (TI * DDIM + TJ * KSTR + TI * TJ * NSTR) * sizeof(float);
    cudaFuncSetAttribute(attn_kernel, cudaFuncAttributeMaxDynamicSharedMemorySize,
                         (int)smem_bytes);
    attn_kernel<<<BATCH * 64 * 2, NTHR, smem_bytes>>>(w_mlp, b_mlp);

    merge_kernel<<<BATCH * 64, 256>>>(out);
}

// round 11
// speedup vs baseline: 1.0980x; 1.0205x over previous
#include <cuda_runtime.h>
#include <cstdint>

#define L1LEN 512
#define L2LEN 512
#define DDIM  256
#define BATCH 2
#define NG    16
#define GS    16
#define TI    8
#define TJ    32           // source rows per tile
#define NHALF 8            // tiles per CTA (256 j per CTA half)
#define KSTR  256          // V row stride (floats)
#define NSTR  20           // sc2 inner stride
#define NTHR  256

__device__ float g_Q[BATCH * L1LEN * DDIM];
__device__ float g_K[BATCH * L2LEN * DDIM];
__device__ float g_V[BATCH * L2LEN * DDIM];
__device__ float g_pacc[BATCH * 64 * 2 * TI * DDIM];   // partial outputs
__device__ float g_pl[BATCH * 64 * 2 * TI * NG];       // partial exp-sums

// ---------------------------------------------------------------------------
// f32x2 packed helpers (Blackwell): FFMA2 / FADD2 via PTX
// ---------------------------------------------------------------------------
__device__ __forceinline__ unsigned long long fma2u(unsigned long long a,
                                                    unsigned long long b,
                                                    unsigned long long c) {
    unsigned long long r;
    asm("fma.rn.f32x2 %0, %1, %2, %3;" : "=l"(r) : "l"(a), "l"(b), "l"(c));
    return r;
}

// acc += relu(q2 + nk2) * w2   (elementwise packed; relu on scalar halves)
__device__ __forceinline__ void relu_fma(unsigned long long& acc,
                                         unsigned long long q2,
                                         unsigned long long nk2,
                                         unsigned long long w2) {
    asm("{\n\t"
        ".reg .b64 d;\n\t"
        ".reg .f32 lo, hi;\n\t"
        "add.rn.f32x2 d, %1, %2;\n\t"
        "mov.b64 {lo, hi}, d;\n\t"
        "max.f32 lo, lo, 0f00000000;\n\t"
        "max.f32 hi, hi, 0f00000000;\n\t"
        "mov.b64 d, {lo, hi};\n\t"
        "fma.rn.f32x2 %0, d, %3, %0;\n\t"
        "}"
        : "+l"(acc) : "l"(q2), "l"(nk2), "l"(w2));
}

__device__ __forceinline__ unsigned long long pk2(float a, float b) {
    unsigned long long r;
    asm("mov.b64 %0, {%1, %2};" : "=l"(r) : "f"(a), "f"(b));
    return r;
}

__device__ __forceinline__ float2 upk2(unsigned long long v) {
    float2 r;
    asm("mov.b64 {%0, %1}, %2;" : "=f"(r.x), "=f"(r.y) : "l"(v));
    return r;
}

// ---------------------------------------------------------------------------
// QKV projection via tensor cores, 3xTF32 error-compensated (unchanged R10).
// ---------------------------------------------------------------------------
__device__ __forceinline__ uint32_t f2tf32(float f) {
    uint32_t r;
    asm("cvt.rna.tf32.f32 %0, %1;" : "=r"(r) : "f"(f));
    return r;
}

__device__ __forceinline__ void mma_tf32(float* c, const uint32_t* a,
                                         uint32_t b0, uint32_t b1) {
    asm("mma.sync.aligned.m16n8k8.row.col.f32.tf32.tf32.f32 "
        "{%0,%1,%2,%3}, {%4,%5,%6,%7}, {%8,%9}, {%0,%1,%2,%3};"
        : "+f"(c[0]), "+f"(c[1]), "+f"(c[2]), "+f"(c[3])
        : "r"(a[0]), "r"(a[1]), "r"(a[2]), "r"(a[3]), "r"(b0), "r"(b1));
}

__global__ __launch_bounds__(128) void qkv_gemm(const float* __restrict__ x_target,
                                                const float* __restrict__ x_source,
                                                const float* __restrict__ Wq,
                                                const float* __restrict__ Wk,
                                                const float* __restrict__ Wv) {
    const int z = blockIdx.z;
    const float* __restrict__ x = (z == 0) ? x_target : x_source;
    const float* __restrict__ W = (z == 0) ? Wq : ((z == 1) ? Wk : Wv);
    float* __restrict__ y       = (z == 0) ? g_Q : ((z == 1) ? g_K : g_V);

    __shared__ float    xs[64][36];
    __shared__ uint32_t wsh[32][36];
    __shared__ uint32_t wsl[32][36];

    const int t    = threadIdx.x;
    const int warp = t >> 5;
    const int lane = t & 31;
    const int gid  = lane >> 2;
    const int tig  = lane & 3;
    const int m_blk = blockIdx.x * 64;
    const int n_blk = blockIdx.y * 32;

    float acc[4][4] = {};

    for (int chunk = 0; chunk < 8; chunk++) {
        const int kc = chunk * 32;
        __syncthreads();
#pragma unroll
        for (int i = 0; i < 4; i++) {
            int idx = t + i * 128;
            int row = idx >> 3, col = (idx & 7) * 4;
            *(float4*)&xs[row][col] =
                *(const float4*)&x[(m_blk + row) * DDIM + kc + col];
        }
#pragma unroll
        for (int i = 0; i < 2; i++) {
            int idx = t + i * 128;
            int row = idx >> 3, col = (idx & 7) * 4;
            float4 wv = *(const float4*)&W[(n_blk + row) * DDIM + kc + col];
            uint32_t h0 = f2tf32(wv.x), h1 = f2tf32(wv.y);
            uint32_t h2 = f2tf32(wv.z), h3 = f2tf32(wv.w);
            wsh[row][col + 0] = h0; wsh[row][col + 1] = h1;
            wsh[row][col + 2] = h2; wsh[row][col + 3] = h3;
            wsl[row][col + 0] = f2tf32(wv.x - __uint_as_float(h0));
            wsl[row][col + 1] = f2tf32(wv.y - __uint_as_float(h1));
            wsl[row][col + 2] = f2tf32(wv.z - __uint_as_float(h2));
            wsl[row][col + 3] = f2tf32(wv.w - __uint_as_float(h3));
        }
        __syncthreads();

#pragma unroll
        for (int ks = 0; ks < 4; ks++) {
            const int k0 = ks * 8;
            float af[4];
            af[0] = xs[warp * 16 + gid][k0 + tig];
            af[1] = xs[warp * 16 + gid + 8][k0 + tig];
            af[2] = xs[warp * 16 + gid][k0 + tig + 4];
            af[3] = xs[warp * 16 + gid + 8][k0 + tig + 4];
            uint32_t ahi[4], alo[4];
#pragma unroll
            for (int j = 0; j < 4; j++) {
                ahi[j] = f2tf32(af[j]);
                alo[j] = f2tf32(af[j] - __uint_as_float(ahi[j]));
            }
#pragma unroll
            for (int nb = 0; nb < 4; nb++) {
                uint32_t bhi0 = wsh[nb * 8 + gid][k0 + tig];
                uint32_t bhi1 = wsh[nb * 8 + gid][k0 + tig + 4];
                uint32_t blo0 = wsl[nb * 8 + gid][k0 + tig];
                uint32_t blo1 = wsl[nb * 8 + gid][k0 + tig + 4];
                mma_tf32(acc[nb], ahi, bhi0, bhi1);
                mma_tf32(acc[nb], ahi, blo0, blo1);
                mma_tf32(acc[nb], alo, bhi0, bhi1);
            }
        }
    }

    const int m = m_blk + warp * 16 + gid;
#pragma unroll
    for (int nb = 0; nb < 4; nb++) {
        const int n = n_blk + nb * 8 + 2 * tig;
        *(float2*)&y[m * DDIM + n]       = make_float2(acc[nb][0], acc[nb][1]);
        *(float2*)&y[(m + 8) * DDIM + n] = make_float2(acc[nb][2], acc[nb][3]);
    }
}

// ---------------------------------------------------------------------------
// Fused attention, f32x2-packed math, j-split across 2 CTAs, no-max softmax.
// 256 threads, 2 CTAs/SM. Grid 256 = BATCH * 64 * 2.
//   B: thread (jj, nc): packed relu-fma scores, 8 i x 2 groups -> sc2 (exp'd)
//   D: warp (ih, jq): 4 i-rows x 8 j x 256 d, FFMA2 accumulate
// ---------------------------------------------------------------------------
__global__ __launch_bounds__(NTHR, 2) void attn_kernel(const float* __restrict__ wmlp,
                                                       const float* __restrict__ bmlp) {
    extern __shared__ float sm[];
    float* q   = sm;                        // 2048
    float* vt  = q + TI * DDIM;             // 32*256 = 8192 (reused as scratch)
    float* sc2 = vt + TJ * KSTR;            // 8*32*20 = 5120  [(i*TJ+j)*NSTR + n]

    const int t     = threadIdx.x;
    const int bx    = blockIdx.x;
    const int b     = bx >> 7;
    const int itile = (bx >> 1) & 63;
    const int jh2   = bx & 1;               // j half
    const int i_base = itile * TI;
    const int part   = bx;

    const int jj = t & 31;
    const int nc = t >> 5;                  // 0..7 -> groups 2nc, 2nc+1
    const int qp = t & 31;
    const int ih = (t >> 5) & 1;            // i rows 4*ih .. 4*ih+3
    const int jq = t >> 6;                  // j quarter (8 j each)
    const int n0 = (4 * qp) & 15;

    const float b0 = bmlp[0];
    // packed MLP weights (same for every group)
    unsigned long long w2[8];
#pragma unroll
    for (int p = 0; p < 8; p++) w2[p] = pk2(wmlp[2 * p], wmlp[2 * p + 1]);

    {
        const float* Qg = g_Q + (b * L1LEN + i_base) * DDIM;
#pragma unroll
        for (int it = 0; it < 2; it++) {
            int idx = t + it * NTHR;
            int row = idx >> 6, col = (idx & 63) * 4;
            *(float4*)&q[row * DDIM + col] = *(const float4*)&Qg[row * DDIM + col];
        }
    }

    ulonglong2 acc2[4][2];                  // [i-row r][v-quad]: packed d-pairs
#pragma unroll
    for (int r = 0; r < 4; r++) {
        acc2[r][0].x = 0ull; acc2[r][0].y = 0ull;
        acc2[r][1].x = 0ull; acc2[r][1].y = 0ull;
    }
    float lsum = 0.f;

    for (int tile = 0; tile < NHALF; tile++) {
        __syncthreads();
        const int j_glob = jh2 * (L2LEN / 2) + tile * TJ;
        // ---- Phase A: stage V tile (overlaps with B; no barrier between)
        {
            const float* Vg = g_V + (b * L2LEN + j_glob) * DDIM;
#pragma unroll
            for (int it = 0; it < (TJ * DDIM / 4) / NTHR; it++) {
                int idx = t + it * NTHR;
                int row = idx >> 6, col = (idx & 63) * 4;
                *(float4*)&vt[row * KSTR + col] = *(const float4*)&Vg[row * DDIM + col];
            }
        }

        // ---- Phase B: packed scores + exp -> sc2
#pragma unroll
        for (int n2 = 0; n2 < 2; n2++) {
            const int n = nc * 2 + n2;
            const float* kr = g_K + (b * L2LEN + j_glob + jj) * DDIM + n * GS;
            unsigned long long nk2[8];
#pragma unroll
            for (int dq = 0; dq < 4; dq++) {
                float4 kq = *(const float4*)&kr[dq * 4];
                nk2[dq * 2]     = pk2(-kq.x, -kq.y);
                nk2[dq * 2 + 1] = pk2(-kq.z, -kq.w);
            }
            unsigned long long s2[8];
#pragma unroll
            for (int i = 0; i < 8; i++) s2[i] = 0ull;
#pragma unroll
            for (int dq = 0; dq < 4; dq++) {
#pragma unroll
                for (int i = 0; i < 8; i++) {
                    const ulonglong2 qv =
                        *(const ulonglong2*)&q[i * DDIM + n * GS + dq * 4];
                    relu_fma(s2[i], qv.x, nk2[dq * 2], w2[dq * 2]);
                    relu_fma(s2[i], qv.y, nk2[dq * 2 + 1], w2[dq * 2 + 1]);
                }
            }
#pragma unroll
            for (int i = 0; i < 8; i++) {
                float2 f = upk2(s2[i]);
                sc2[(i * TJ + jj) * NSTR + n] =
                    __expf(fmaxf(f.x + f.y + b0, 0.f));
            }
        }
        __syncthreads();

        // ---- exp-sum (t<128, overlaps with D)
        if (t < TI * NG) {
            const int ci = t >> 4, cn = t & 15;
            const float* base = sc2 + ci * TJ * NSTR + cn;
            float s0 = 0.f, s1 = 0.f;
#pragma unroll
            for (int j = 0; j < TJ; j += 2) {
                s0 += base[j * NSTR];
                s1 += base[(j + 1) * NSTR];
            }
            lsum += s0 + s1;
        }

        // ---- Phase D: FFMA2 accumulate; warp (ih,jq): 4 i x 8 j x 256 d
        {
            const int j0 = jq * 8;
#pragma unroll
            for (int jo = 0; jo < 8; jo++) {
                const int j = j0 + jo;
                const ulonglong2 v0 = *(const ulonglong2*)&vt[j * KSTR + 4 * qp];
                const ulonglong2 v1 =
                    *(const ulonglong2*)&vt[j * KSTR + 4 * qp + 128];
#pragma unroll
                for (int r = 0; r < 4; r++) {
                    const ulonglong2 p = *(const ulonglong2*)
                        &sc2[((4 * ih + r) * TJ + j) * NSTR + n0];
                    acc2[r][0].x = fma2u(p.x, v0.x, acc2[r][0].x);
                    acc2[r][0].y = fma2u(p.y, v0.y, acc2[r][0].y);
                    acc2[r][1].x = fma2u(p.x, v1.x, acc2[r][1].x);
                    acc2[r][1].y = fma2u(p.y, v1.y, acc2[r][1].y);
                }
            }
        }
    }

    // ---- reduce jq partials via vt scratch, write partials to global
    __syncthreads();
    {
        float* scr = vt;   // warp w slot: w*1024 + qp*32 + r*8 (+4)
        int base = (t >> 5) * 1024 + qp * 32;
#pragma unroll
        for (int r = 0; r < 4; r++) {
            *(float4*)&scr[base + r * 8]     = *(float4*)&acc2[r][0];
            *(float4*)&scr[base + r * 8 + 4] = *(float4*)&acc2[r][1];
        }
    }
    __syncthreads();
    {
        // thread t owns (i = t>>5, qp = t&31); warp for (ih,jq) = ih + 2*jq
        const int i   = t >> 5;
        const int mih = i >> 2, r = i & 3;
        const float* scr = vt;
        float4 s0 = make_float4(0.f, 0.f, 0.f, 0.f);
        float4 s1 = make_float4(0.f, 0.f, 0.f, 0.f);
#pragma unroll
        for (int jqq = 0; jqq < 4; jqq++) {
            const int wv = mih + 2 * jqq;
            const float* pbase = scr + wv * 1024 + (t & 31) * 32 + r * 8;
            float4 a0 = *(const float4*)&pbase[0];
            float4 a1 = *(const float4*)&pbase[4];
            s0.x += a0.x; s0.y += a0.y; s0.z += a0.z; s0.w += a0.w;
            s1.x += a1.x; s1.y += a1.y; s1.z += a1.z; s1.w += a1.w;
        }
        float* pb = g_pacc + part * (TI * DDIM);
        *(float4*)&pb[i * DDIM + 4 * (t & 31)]       = s0;
        *(float4*)&pb[i * DDIM + 4 * (t & 31) + 128] = s1;
    }
    if (t < TI * NG) g_pl[part * (TI * NG) + t] = lsum;
}

// ---------------------------------------------------------------------------
// Merge: out = (acc_half0 + acc_half1) / (l_half0 + l_half1)
// ---------------------------------------------------------------------------
__global__ __launch_bounds__(256) void merge_kernel(float* __restrict__ out) {
    const int bx = blockIdx.x;
    const int t  = threadIdx.x;
    const int p0 = bx * 2, p1 = bx * 2 + 1;
    const float* a0 = g_pacc + p0 * (TI * DDIM);
    const float* a1 = g_pacc + p1 * (TI * DDIM);
    const float* l0 = g_pl + p0 * (TI * NG);
    const float* l1 = g_pl + p1 * (TI * NG);
    float* ob = out + bx * (TI * DDIM);

#pragma unroll
    for (int k = 0; k < 2; k++) {
        int idx = t + k * 256;
        int i   = idx >> 6;
        int d0  = (idx & 63) * 4;
        int nq  = d0 & 15;
        float4 x0 = *(const float4*)&a0[i * DDIM + d0];
        float4 x1 = *(const float4*)&a1[i * DDIM + d0];
        float4 u0 = *(const float4*)&l0[i * NG + nq];
        float4 u1 = *(const float4*)&l1[i * NG + nq];
        float4 r;
        r.x = (x0.x + x1.x) / (u0.x + u1.x);
        r.y = (x0.y + x1.y) / (u0.y + u1.y);
        r.z = (x0.z + x1.z) / (u0.z + u1.z);
        r.w = (x0.w + x1.w) / (u0.w + u1.w);
        *(float4*)&ob[i * DDIM + d0] = r;
    }
}

// ---------------------------------------------------------------------------
extern "C" void kernel_launch(void* const* d_in, const int* in_sizes, int n_in,
                              void* d_out, int out_size) {
    const float* x_source = (const float*)d_in[0];
    const float* x_target = (const float*)d_in[1];
    const float* Wq       = (const float*)d_in[2];
    const float* Wk       = (const float*)d_in[3];
    const float* Wv       = (const float*)d_in[4];
    const float* w_mlp    = (const float*)d_in[5];
    const float* b_mlp    = (const float*)d_in[6];
    float* out            = (float*)d_out;

    dim3 ggrid(16, 8, 3);
    qkv_gemm<<<ggrid, 128>>>(x_target, x_source, Wq, Wk, Wv);

    const size_t smem_bytes =
        (TI * DDIM + TJ * KSTR + TI * TJ * NSTR) * sizeof(float);
    cudaFuncSetAttribute(attn_kernel, cudaFuncAttributeMaxDynamicSharedMemorySize,
                         (int)smem_bytes);
    attn_kernel<<<BATCH * 64 * 2, NTHR, smem_bytes>>>(w_mlp, b_mlp);

    merge_kernel<<<BATCH * 64, 256>>>(out);
}